// round 7
// baseline (speedup 1.0000x reference)
#include <cuda_runtime.h>
#include <cuda_bf16.h>
#include <cstdint>

#define D      256
#define MAXN   8192
#define BM     128                 // rows per CTA
#define BN     128                 // cols per tile
#define CSPLIT 2                   // column splits
#define NT     ((MAXN / CSPLIT) / BN)   // 32 tiles per CTA
#define LOG2E_OVER_T 28.853900817779268f
#define INV_T        20.0f

// SMEM layout (bytes)
#define SM_PART 0                  // 2 x 128 floats
#define SM_A    2048               // 128 rows x 512 B (swizzled)  = 65536
#define SM_B0   (SM_A + 65536)
#define SM_TOTAL (SM_B0 + 2 * 65536)   // 198656

// ---------------- scratch -------------------------------------------------
__device__ __align__(16) __nv_bfloat16 g_a[MAXN * D];
__device__ __align__(16) __nv_bfloat16 g_b[MAXN * D];
__device__ float g_diag[MAXN];
__device__ float g_part[MAXN * CSPLIT];

// ---------------- helpers --------------------------------------------------
__device__ __forceinline__ uint32_t smem_u32(const void* p) {
    return (uint32_t)__cvta_generic_to_shared(p);
}
__device__ __forceinline__ void cp_async16(uint32_t sdst, const void* gsrc) {
    asm volatile("cp.async.cg.shared.global [%0], [%1], 16;\n" :: "r"(sdst), "l"(gsrc));
}
#define CP_COMMIT() asm volatile("cp.async.commit_group;\n" ::: "memory")
#define CP_WAIT1()  asm volatile("cp.async.wait_group 1;\n" ::: "memory")

__device__ __forceinline__ float ex2f(float x) {
    float y; asm("ex2.approx.f32 %0, %1;" : "=f"(y) : "f"(x)); return y;
}
__device__ __forceinline__ void ldsm_x4(uint32_t r[4], uint32_t addr) {
    asm volatile("ldmatrix.sync.aligned.m8n8.x4.shared.b16 {%0,%1,%2,%3}, [%4];"
                 : "=r"(r[0]), "=r"(r[1]), "=r"(r[2]), "=r"(r[3]) : "r"(addr));
}
__device__ __forceinline__ void mma_bf16(float c[4], const uint32_t a[4],
                                         uint32_t b0, uint32_t b1) {
    asm volatile(
        "mma.sync.aligned.m16n8k16.row.col.f32.bf16.bf16.f32 "
        "{%0,%1,%2,%3}, {%4,%5,%6,%7}, {%8,%9}, {%0,%1,%2,%3};\n"
        : "+f"(c[0]), "+f"(c[1]), "+f"(c[2]), "+f"(c[3])
        : "r"(a[0]), "r"(a[1]), "r"(a[2]), "r"(a[3]), "r"(b0), "r"(b1));
}

// cp.async loader: 128x256 bf16 tile (64KB), XOR-swizzled 16B chunks, 256 threads
__device__ __forceinline__ void load_tile(uint32_t sdst_base,
                                          const __nv_bfloat16* gsrc, int tid) {
    int c = tid & 31, r8 = tid >> 5;            // chunk 0..31, row group 0..7
    #pragma unroll
    for (int p = 0; p < 16; p++) {
        int row = p * 8 + r8;
        uint32_t sdst = sdst_base + row * 512 + (((uint32_t)(c ^ (row & 7))) << 4);
        cp_async16(sdst, gsrc + (size_t)row * D + c * 8);
    }
}

// ---------------- kernel 1: norms + exact diagonal (warp per row) ----------
__global__ void norm_kernel(const float4* __restrict__ a4, const float4* __restrict__ b4) {
    int w = threadIdx.x >> 5, lane = threadIdx.x & 31;
    int row = blockIdx.x * 8 + w;
    const float4* ar = a4 + (size_t)row * (D / 4);
    const float4* br = b4 + (size_t)row * (D / 4);
    float4 a0 = ar[lane * 2], a1 = ar[lane * 2 + 1];
    float4 b0 = br[lane * 2], b1 = br[lane * 2 + 1];

    float sa = a0.x*a0.x + a0.y*a0.y + a0.z*a0.z + a0.w*a0.w
             + a1.x*a1.x + a1.y*a1.y + a1.z*a1.z + a1.w*a1.w;
    float sb = b0.x*b0.x + b0.y*b0.y + b0.z*b0.z + b0.w*b0.w
             + b1.x*b1.x + b1.y*b1.y + b1.z*b1.z + b1.w*b1.w;
    float sd = a0.x*b0.x + a0.y*b0.y + a0.z*b0.z + a0.w*b0.w
             + a1.x*b1.x + a1.y*b1.y + a1.z*b1.z + a1.w*b1.w;
    #pragma unroll
    for (int o = 16; o; o >>= 1) {
        sa += __shfl_xor_sync(0xffffffffu, sa, o);
        sb += __shfl_xor_sync(0xffffffffu, sb, o);
        sd += __shfl_xor_sync(0xffffffffu, sd, o);
    }
    float ia = rsqrtf(fmaxf(sa, 1e-16f));
    float ib = rsqrtf(fmaxf(sb, 1e-16f));
    if (lane == 0) g_diag[row] = sd * ia * ib * INV_T;

    float fa = ia * LOG2E_OVER_T;
    __nv_bfloat162 p0 = __floats2bfloat162_rn(a0.x*fa, a0.y*fa);
    __nv_bfloat162 p1 = __floats2bfloat162_rn(a0.z*fa, a0.w*fa);
    __nv_bfloat162 p2 = __floats2bfloat162_rn(a1.x*fa, a1.y*fa);
    __nv_bfloat162 p3 = __floats2bfloat162_rn(a1.z*fa, a1.w*fa);
    uint4 ua = { *(uint32_t*)&p0, *(uint32_t*)&p1, *(uint32_t*)&p2, *(uint32_t*)&p3 };
    *(uint4*)(g_a + (size_t)row * D + lane * 8) = ua;

    __nv_bfloat162 q0 = __floats2bfloat162_rn(b0.x*ib, b0.y*ib);
    __nv_bfloat162 q1 = __floats2bfloat162_rn(b0.z*ib, b0.w*ib);
    __nv_bfloat162 q2 = __floats2bfloat162_rn(b1.x*ib, b1.y*ib);
    __nv_bfloat162 q3 = __floats2bfloat162_rn(b1.z*ib, b1.w*ib);
    uint4 ub = { *(uint32_t*)&q0, *(uint32_t*)&q1, *(uint32_t*)&q2, *(uint32_t*)&q3 };
    *(uint4*)(g_b + (size_t)row * D + lane * 8) = ub;
}

// ---------------- kernel 2: ldmatrix + HMMA GEMM + pipelined ex2 -----------
// 256 threads = 8 warps, 4x2 warp grid, 32x64 warp tile, CTA tile 128x128.
// acc is double-buffered: tile t's MMA loop interleaves ex2 of tile t-1's
// accumulators (4 per kk step), hiding the MUFU epilogue under HMMA.
__global__ __launch_bounds__(256, 1) void sim_lse_kernel() {
    extern __shared__ char sm[];
    uint32_t sbase = smem_u32(sm);
    int tid = threadIdx.x, w = tid >> 5, lane = tid & 31;
    int rb = blockIdx.x >> 1, cs = blockIdx.x & 1;
    int rowBase = rb * BM;
    int col0 = cs * (MAXN / CSPLIT);

    int wr = (w & 3) * 32;        // warp row offset: 0/32/64/96
    int wc = (w >> 2) * 64;       // warp col offset: 0/64
    int g  = lane >> 3, l3 = lane & 7;
    uint32_t rk = (uint32_t)(l3 >> 1);       // XOR term for 32B k-chunk pair

    // ldmatrix base addresses (verified R3 layout)
    uint32_t abase[2], boff[4];
    {
        uint32_t c0a = (uint32_t)(((g >> 1) ^ (l3 & 1)) << 4);
        uint32_t c0b = (uint32_t)(((g & 1) ^ (l3 & 1)) << 4);
        #pragma unroll
        for (int mt = 0; mt < 2; mt++) {
            int row = wr + mt * 16 + (g & 1) * 8 + l3;
            abase[mt] = sbase + SM_A + row * 512 + c0a;
        }
        #pragma unroll
        for (int nt = 0; nt < 4; nt++) {
            int n = wc + nt * 16 + (g >> 1) * 8 + l3;
            boff[nt] = (uint32_t)(n * 512) + c0b;
        }
    }

    // prologue: A tile + B tile 0
    load_tile(sbase + SM_A,  g_a + (size_t)rowBase * D, tid);
    load_tile(sbase + SM_B0, g_b + (size_t)col0 * D,   tid);
    CP_COMMIT();

    float acc[2][2][8][4];        // [buf][mt][nt][c]
    #pragma unroll
    for (int bb = 0; bb < 2; bb++)
        #pragma unroll
        for (int mt = 0; mt < 2; mt++)
            #pragma unroll
            for (int j = 0; j < 8; j++)
                acc[bb][mt][j][0] = acc[bb][mt][j][1] =
                acc[bb][mt][j][2] = acc[bb][mt][j][3] = 0.f;
    float rs0[2] = {0, 0}, rs1[2] = {0, 0};

    for (int t = 0; t < NT; t++) {
        __syncthreads();           // all reads of buf[(t+1)&1] (iter t-1) done
        if (t + 1 < NT)
            load_tile(sbase + SM_B0 + ((t + 1) & 1) * 65536,
                      g_b + (size_t)(col0 + (t + 1) * BN) * D, tid);
        CP_COMMIT();               // empty group on last iter keeps wait_group 1 valid
        CP_WAIT1();                // group t retired -> buf[t&1] ready
        __syncthreads();

        uint32_t bbuf = sbase + SM_B0 + (t & 1) * 65536;
        int cur = t & 1, prev = cur ^ 1;

        #pragma unroll
        for (int kk = 0; kk < 16; kk++) {
            uint32_t koff = ((uint32_t)(kk ^ rk)) << 5;
            uint32_t af[2][4], bf[4][4];
            #pragma unroll
            for (int mt = 0; mt < 2; mt++) ldsm_x4(af[mt], abase[mt] + koff);
            #pragma unroll
            for (int nt = 0; nt < 4; nt++) ldsm_x4(bf[nt], bbuf + boff[nt] + koff);
            #pragma unroll
            for (int mt = 0; mt < 2; mt++) {
                #pragma unroll
                for (int nt = 0; nt < 4; nt++) {
                    mma_bf16(acc[cur][mt][nt * 2],     af[mt], bf[nt][0], bf[nt][1]);
                    mma_bf16(acc[cur][mt][nt * 2 + 1], af[mt], bf[nt][2], bf[nt][3]);
                }
            }
            // interleaved epilogue of tile t-1: 4 elements per kk (64 total)
            if (t > 0) {
                #pragma unroll
                for (int j = 0; j < 4; j++) {
                    int e  = kk * 4 + j;
                    int mt = e >> 5, nt = (e >> 2) & 7, c = e & 3;
                    float v = ex2f(acc[prev][mt][nt][c]);
                    if (c < 2) rs0[mt] += v; else rs1[mt] += v;
                    acc[prev][mt][nt][c] = 0.f;   // ready for reuse at tile t+1
                }
            }
        }
    }

    // tail epilogue: last tile's accumulators
    {
        int prev = (NT - 1) & 1;
        #pragma unroll
        for (int mt = 0; mt < 2; mt++)
            #pragma unroll
            for (int j = 0; j < 8; j++) {
                rs0[mt] += ex2f(acc[prev][mt][j][0]) + ex2f(acc[prev][mt][j][1]);
                rs1[mt] += ex2f(acc[prev][mt][j][2]) + ex2f(acc[prev][mt][j][3]);
            }
    }

    // reduce across 4 lanes sharing each row, then across the 2 warp-columns
    #pragma unroll
    for (int mt = 0; mt < 2; mt++) {
        rs0[mt] += __shfl_xor_sync(0xffffffffu, rs0[mt], 1);
        rs0[mt] += __shfl_xor_sync(0xffffffffu, rs0[mt], 2);
        rs1[mt] += __shfl_xor_sync(0xffffffffu, rs1[mt], 1);
        rs1[mt] += __shfl_xor_sync(0xffffffffu, rs1[mt], 2);
    }
    float* partial = (float*)(sm + SM_PART);
    if ((lane & 3) == 0) {
        int half = (w >> 2) * 128;
        #pragma unroll
        for (int mt = 0; mt < 2; mt++) {
            partial[half + wr + mt * 16 + (lane >> 2)]     = rs0[mt];
            partial[half + wr + mt * 16 + 8 + (lane >> 2)] = rs1[mt];
        }
    }
    __syncthreads();
    if (tid < 128)
        g_part[(size_t)(rowBase + tid) * CSPLIT + cs] = partial[tid] + partial[128 + tid];
}

// ---------------- kernel 3: final loss ------------------------------------
__global__ void reduce_kernel(float* __restrict__ out, int N) {
    __shared__ float s[1024];
    int t = threadIdx.x;
    float acc = 0.f;
    for (int i = t; i < N; i += 1024) {
        float sum2 = g_part[i * CSPLIT] + g_part[i * CSPLIT + 1];
        acc += __logf(sum2) - g_diag[i];       // log(sum 2^l2) = LSE (natural)
    }
    s[t] = acc;
    __syncthreads();
    for (int o = 512; o; o >>= 1) {
        if (t < o) s[t] += s[t + o];
        __syncthreads();
    }
    if (t == 0) out[0] = s[0] / (float)N;
}

// ---------------- launch ---------------------------------------------------
extern "C" void kernel_launch(void* const* d_in, const int* in_sizes, int n_in,
                              void* d_out, int out_size) {
    const float* a = (const float*)d_in[0];
    const float* b = (const float*)d_in[1];
    int N = in_sizes[0] / D;   // 8192

    cudaFuncSetAttribute(sim_lse_kernel,
                         cudaFuncAttributeMaxDynamicSharedMemorySize, SM_TOTAL);

    norm_kernel<<<N / 8, 256>>>((const float4*)a, (const float4*)b);
    sim_lse_kernel<<<(N / BM) * CSPLIT, 256, SM_TOTAL>>>();
    reduce_kernel<<<1, 1024>>>((float*)d_out, N);
}

// round 8
// speedup vs baseline: 6.5310x; 6.5310x over previous
#include <cuda_runtime.h>
#include <cuda_bf16.h>
#include <cstdint>

#define D      256
#define MAXN   8192
#define BM     128                 // rows per CTA
#define BN     128                 // cols per tile
#define CSPLIT 2                   // column splits
#define NT     ((MAXN / CSPLIT) / BN)   // 32 tiles per CTA
#define LOG2E_OVER_T 28.853900817779268f
#define INV_T        20.0f

// SMEM layout (bytes)
#define SM_PART 0                  // 2 x 128 floats
#define SM_A    2048               // 128 rows x 512 B (swizzled)  = 65536
#define SM_B0   (SM_A + 65536)
#define SM_TOTAL (SM_B0 + 2 * 65536)   // 198656

// ---------------- scratch -------------------------------------------------
__device__ __align__(16) __nv_bfloat16 g_a[MAXN * D];
__device__ __align__(16) __nv_bfloat16 g_b[MAXN * D];
__device__ float g_diag[MAXN];
__device__ float g_part[MAXN * CSPLIT];

// ---------------- helpers --------------------------------------------------
__device__ __forceinline__ uint32_t smem_u32(const void* p) {
    return (uint32_t)__cvta_generic_to_shared(p);
}
__device__ __forceinline__ void cp_async16(uint32_t sdst, const void* gsrc) {
    asm volatile("cp.async.cg.shared.global [%0], [%1], 16;\n" :: "r"(sdst), "l"(gsrc));
}
#define CP_COMMIT() asm volatile("cp.async.commit_group;\n" ::: "memory")
#define CP_WAIT1()  asm volatile("cp.async.wait_group 1;\n" ::: "memory")

__device__ __forceinline__ float ex2f(float x) {
    float y; asm("ex2.approx.f32 %0, %1;" : "=f"(y) : "f"(x)); return y;
}
__device__ __forceinline__ void ldsm_x4(uint32_t r[4], uint32_t addr) {
    asm volatile("ldmatrix.sync.aligned.m8n8.x4.shared.b16 {%0,%1,%2,%3}, [%4];"
                 : "=r"(r[0]), "=r"(r[1]), "=r"(r[2]), "=r"(r[3]) : "r"(addr));
}
__device__ __forceinline__ void mma_bf16(float c[4], const uint32_t a[4],
                                         uint32_t b0, uint32_t b1) {
    asm volatile(
        "mma.sync.aligned.m16n8k16.row.col.f32.bf16.bf16.f32 "
        "{%0,%1,%2,%3}, {%4,%5,%6,%7}, {%8,%9}, {%0,%1,%2,%3};\n"
        : "+f"(c[0]), "+f"(c[1]), "+f"(c[2]), "+f"(c[3])
        : "r"(a[0]), "r"(a[1]), "r"(a[2]), "r"(a[3]), "r"(b0), "r"(b1));
}

// cp.async loader: 128x256 bf16 tile (64KB), XOR-swizzled 16B chunks, 256 threads
__device__ __forceinline__ void load_tile(uint32_t sdst_base,
                                          const __nv_bfloat16* gsrc, int tid) {
    int c = tid & 31, r8 = tid >> 5;
    #pragma unroll
    for (int p = 0; p < 16; p++) {
        int row = p * 8 + r8;
        uint32_t sdst = sdst_base + row * 512 + (((uint32_t)(c ^ (row & 7))) << 4);
        cp_async16(sdst, gsrc + (size_t)row * D + c * 8);
    }
}

// ---------------- kernel 1: norms + exact diagonal (warp per row) ----------
__global__ void norm_kernel(const float4* __restrict__ a4, const float4* __restrict__ b4) {
    int w = threadIdx.x >> 5, lane = threadIdx.x & 31;
    int row = blockIdx.x * 8 + w;
    const float4* ar = a4 + (size_t)row * (D / 4);
    const float4* br = b4 + (size_t)row * (D / 4);
    float4 a0 = ar[lane * 2], a1 = ar[lane * 2 + 1];
    float4 b0 = br[lane * 2], b1 = br[lane * 2 + 1];

    float sa = a0.x*a0.x + a0.y*a0.y + a0.z*a0.z + a0.w*a0.w
             + a1.x*a1.x + a1.y*a1.y + a1.z*a1.z + a1.w*a1.w;
    float sb = b0.x*b0.x + b0.y*b0.y + b0.z*b0.z + b0.w*b0.w
             + b1.x*b1.x + b1.y*b1.y + b1.z*b1.z + b1.w*b1.w;
    float sd = a0.x*b0.x + a0.y*b0.y + a0.z*b0.z + a0.w*b0.w
             + a1.x*b1.x + a1.y*b1.y + a1.z*b1.z + a1.w*b1.w;
    #pragma unroll
    for (int o = 16; o; o >>= 1) {
        sa += __shfl_xor_sync(0xffffffffu, sa, o);
        sb += __shfl_xor_sync(0xffffffffu, sb, o);
        sd += __shfl_xor_sync(0xffffffffu, sd, o);
    }
    float ia = rsqrtf(fmaxf(sa, 1e-16f));
    float ib = rsqrtf(fmaxf(sb, 1e-16f));
    if (lane == 0) g_diag[row] = sd * ia * ib * INV_T;

    float fa = ia * LOG2E_OVER_T;
    __nv_bfloat162 p0 = __floats2bfloat162_rn(a0.x*fa, a0.y*fa);
    __nv_bfloat162 p1 = __floats2bfloat162_rn(a0.z*fa, a0.w*fa);
    __nv_bfloat162 p2 = __floats2bfloat162_rn(a1.x*fa, a1.y*fa);
    __nv_bfloat162 p3 = __floats2bfloat162_rn(a1.z*fa, a1.w*fa);
    uint4 ua = { *(uint32_t*)&p0, *(uint32_t*)&p1, *(uint32_t*)&p2, *(uint32_t*)&p3 };
    *(uint4*)(g_a + (size_t)row * D + lane * 8) = ua;

    __nv_bfloat162 q0 = __floats2bfloat162_rn(b0.x*ib, b0.y*ib);
    __nv_bfloat162 q1 = __floats2bfloat162_rn(b0.z*ib, b0.w*ib);
    __nv_bfloat162 q2 = __floats2bfloat162_rn(b1.x*ib, b1.y*ib);
    __nv_bfloat162 q3 = __floats2bfloat162_rn(b1.z*ib, b1.w*ib);
    uint4 ub = { *(uint32_t*)&q0, *(uint32_t*)&q1, *(uint32_t*)&q2, *(uint32_t*)&q3 };
    *(uint4*)(g_b + (size_t)row * D + lane * 8) = ub;
}

// ---- one pipeline step: MMA tile into accC; ex2-drain accP (tile t-1) -----
// All array params are references; every index is a compile-time constant
// after unroll, so everything stays in registers (the R7 spill fix).
template<bool DO_EPI>
__device__ __forceinline__ void gemm_step(
    uint32_t sbase, int bufSel, const __nv_bfloat16* nextB, bool doPrefetch,
    int tid, const uint32_t (&abase)[2], const uint32_t (&boff)[4], uint32_t rk,
    float (&accC)[2][8][4], float (&accP)[2][8][4],
    float (&rs0)[2], float (&rs1)[2])
{
    __syncthreads();               // prior reads of the buffer being refilled done
    if (doPrefetch)
        load_tile(sbase + SM_B0 + (bufSel ^ 1) * 65536, nextB, tid);
    CP_COMMIT();                   // (possibly empty group keeps wait_group 1 valid)
    CP_WAIT1();                    // current tile's group retired
    __syncthreads();

    uint32_t bbuf = sbase + SM_B0 + bufSel * 65536;

    #pragma unroll
    for (int kk = 0; kk < 16; kk++) {
        uint32_t koff = ((uint32_t)(kk ^ rk)) << 5;
        uint32_t af[2][4], bf[4][4];
        #pragma unroll
        for (int mt = 0; mt < 2; mt++) ldsm_x4(af[mt], abase[mt] + koff);
        #pragma unroll
        for (int nt = 0; nt < 4; nt++) ldsm_x4(bf[nt], bbuf + boff[nt] + koff);
        #pragma unroll
        for (int mt = 0; mt < 2; mt++) {
            #pragma unroll
            for (int nt = 0; nt < 4; nt++) {
                mma_bf16(accC[mt][nt * 2],     af[mt], bf[nt][0], bf[nt][1]);
                mma_bf16(accC[mt][nt * 2 + 1], af[mt], bf[nt][2], bf[nt][3]);
            }
        }
        if (DO_EPI) {
            // drain 4 elements of the previous tile per kk step (64 total)
            #pragma unroll
            for (int j = 0; j < 4; j++) {
                const int e  = kk * 4 + j;
                const int mt = e >> 5, nt = (e >> 2) & 7, c = e & 3;
                float v = ex2f(accP[mt][nt][c]);
                if (c < 2) rs0[mt] += v; else rs1[mt] += v;
                accP[mt][nt][c] = 0.f;          // recycled for tile t+1
            }
        }
    }
}

// ---------------- kernel 2: ldmatrix + HMMA GEMM + pipelined ex2 -----------
// 256 threads = 8 warps, 4x2 warp grid, 32x64 warp tile, CTA tile 128x128.
__global__ __launch_bounds__(256, 1) void sim_lse_kernel() {
    extern __shared__ char sm[];
    uint32_t sbase = smem_u32(sm);
    int tid = threadIdx.x, w = tid >> 5, lane = tid & 31;
    int rb = blockIdx.x >> 1, cs = blockIdx.x & 1;
    int rowBase = rb * BM;
    int col0 = cs * (MAXN / CSPLIT);

    int wr = (w & 3) * 32;
    int wc = (w >> 2) * 64;
    int g  = lane >> 3, l3 = lane & 7;
    uint32_t rk = (uint32_t)(l3 >> 1);

    uint32_t abase[2], boff[4];
    {
        uint32_t c0a = (uint32_t)(((g >> 1) ^ (l3 & 1)) << 4);
        uint32_t c0b = (uint32_t)(((g & 1) ^ (l3 & 1)) << 4);
        #pragma unroll
        for (int mt = 0; mt < 2; mt++) {
            int row = wr + mt * 16 + (g & 1) * 8 + l3;
            abase[mt] = sbase + SM_A + row * 512 + c0a;
        }
        #pragma unroll
        for (int nt = 0; nt < 4; nt++) {
            int n = wc + nt * 16 + (g >> 1) * 8 + l3;
            boff[nt] = (uint32_t)(n * 512) + c0b;
        }
    }

    // prologue: A tile + B tile 0
    load_tile(sbase + SM_A,  g_a + (size_t)rowBase * D, tid);
    load_tile(sbase + SM_B0, g_b + (size_t)col0 * D,   tid);
    CP_COMMIT();

    float acc0[2][8][4], acc1[2][8][4];
    #pragma unroll
    for (int mt = 0; mt < 2; mt++)
        #pragma unroll
        for (int j = 0; j < 8; j++)
            #pragma unroll
            for (int c = 0; c < 4; c++) { acc0[mt][j][c] = 0.f; acc1[mt][j][c] = 0.f; }
    float rs0[2] = {0, 0}, rs1[2] = {0, 0};

    const __nv_bfloat16* bcol = g_b + (size_t)col0 * D;

    // t = 0 (no epilogue), t = 1 peeled; then pairs with compile-time buffers
    gemm_step<false>(sbase, 0, bcol + (size_t)1 * BN * D, true,
                     tid, abase, boff, rk, acc0, acc1, rs0, rs1);
    gemm_step<true >(sbase, 1, bcol + (size_t)2 * BN * D, NT > 2,
                     tid, abase, boff, rk, acc1, acc0, rs0, rs1);
    for (int t = 2; t < NT; t += 2) {
        gemm_step<true>(sbase, 0, bcol + (size_t)(t + 1) * BN * D, true,
                        tid, abase, boff, rk, acc0, acc1, rs0, rs1);
        gemm_step<true>(sbase, 1, bcol + (size_t)(t + 2) * BN * D, t + 2 < NT,
                        tid, abase, boff, rk, acc1, acc0, rs0, rs1);
    }

    // tail epilogue: last tile (odd index -> acc1)
    #pragma unroll
    for (int mt = 0; mt < 2; mt++)
        #pragma unroll
        for (int j = 0; j < 8; j++) {
            rs0[mt] += ex2f(acc1[mt][j][0]) + ex2f(acc1[mt][j][1]);
            rs1[mt] += ex2f(acc1[mt][j][2]) + ex2f(acc1[mt][j][3]);
        }

    // reduce across 4 lanes sharing each row, then across the 2 warp-columns
    #pragma unroll
    for (int mt = 0; mt < 2; mt++) {
        rs0[mt] += __shfl_xor_sync(0xffffffffu, rs0[mt], 1);
        rs0[mt] += __shfl_xor_sync(0xffffffffu, rs0[mt], 2);
        rs1[mt] += __shfl_xor_sync(0xffffffffu, rs1[mt], 1);
        rs1[mt] += __shfl_xor_sync(0xffffffffu, rs1[mt], 2);
    }
    float* partial = (float*)(sm + SM_PART);
    if ((lane & 3) == 0) {
        int half = (w >> 2) * 128;
        #pragma unroll
        for (int mt = 0; mt < 2; mt++) {
            partial[half + wr + mt * 16 + (lane >> 2)]     = rs0[mt];
            partial[half + wr + mt * 16 + 8 + (lane >> 2)] = rs1[mt];
        }
    }
    __syncthreads();
    if (tid < 128)
        g_part[(size_t)(rowBase + tid) * CSPLIT + cs] = partial[tid] + partial[128 + tid];
}

// ---------------- kernel 3: final loss ------------------------------------
__global__ void reduce_kernel(float* __restrict__ out, int N) {
    __shared__ float s[1024];
    int t = threadIdx.x;
    float acc = 0.f;
    for (int i = t; i < N; i += 1024) {
        float sum2 = g_part[i * CSPLIT] + g_part[i * CSPLIT + 1];
        acc += __logf(sum2) - g_diag[i];
    }
    s[t] = acc;
    __syncthreads();
    for (int o = 512; o; o >>= 1) {
        if (t < o) s[t] += s[t + o];
        __syncthreads();
    }
    if (t == 0) out[0] = s[0] / (float)N;
}

// ---------------- launch ---------------------------------------------------
extern "C" void kernel_launch(void* const* d_in, const int* in_sizes, int n_in,
                              void* d_out, int out_size) {
    const float* a = (const float*)d_in[0];
    const float* b = (const float*)d_in[1];
    int N = in_sizes[0] / D;   // 8192

    cudaFuncSetAttribute(sim_lse_kernel,
                         cudaFuncAttributeMaxDynamicSharedMemorySize, SM_TOTAL);

    norm_kernel<<<N / 8, 256>>>((const float4*)a, (const float4*)b);
    sim_lse_kernel<<<(N / BM) * CSPLIT, 256, SM_TOTAL>>>();
    reduce_kernel<<<1, 1024>>>((float*)d_out, N);
}

// round 9
// speedup vs baseline: 7.1449x; 1.0940x over previous
#include <cuda_runtime.h>
#include <cuda_bf16.h>
#include <cstdint>

#define D      256
#define MAXN   8192
#define BM     128                 // rows per row-block
#define BN     128                 // cols per tile
#define CTPB   64                  // col-tiles per row-block (MAXN/BN)
#define NTOT   4096                // total tiles = 64 rb x 64 ct
#define GRIDZ  148                 // one CTA per SM
#define SLOTS  4                   // max CTAs sharing one row-block
#define LOG2E_OVER_T 28.853900817779268f
#define INV_T        20.0f

// SMEM layout (bytes)
#define SM_PART 0                  // 2 x 128 floats
#define SM_A    2048               // 128 rows x 512 B (swizzled) = 65536
#define SM_B0   (SM_A + 65536)
#define SM_TOTAL (SM_B0 + 2 * 65536)   // 198656

// ---------------- scratch -------------------------------------------------
__device__ __align__(16) __nv_bfloat16 g_a[MAXN * D];
__device__ __align__(16) __nv_bfloat16 g_b[MAXN * D];
__device__ float g_diag[MAXN];
__device__ float g_part[MAXN * SLOTS];

// ---------------- helpers --------------------------------------------------
__device__ __forceinline__ uint32_t smem_u32(const void* p) {
    return (uint32_t)__cvta_generic_to_shared(p);
}
__device__ __forceinline__ void cp_async16(uint32_t sdst, const void* gsrc) {
    asm volatile("cp.async.cg.shared.global [%0], [%1], 16;\n" :: "r"(sdst), "l"(gsrc));
}
#define CP_COMMIT() asm volatile("cp.async.commit_group;\n" ::: "memory")
#define CP_WAIT1()  asm volatile("cp.async.wait_group 1;\n" ::: "memory")

__device__ __forceinline__ float ex2f(float x) {
    float y; asm("ex2.approx.f32 %0, %1;" : "=f"(y) : "f"(x)); return y;
}
__device__ __forceinline__ void ldsm_x4(uint32_t r[4], uint32_t addr) {
    asm volatile("ldmatrix.sync.aligned.m8n8.x4.shared.b16 {%0,%1,%2,%3}, [%4];"
                 : "=r"(r[0]), "=r"(r[1]), "=r"(r[2]), "=r"(r[3]) : "r"(addr));
}
__device__ __forceinline__ void mma_bf16(float c[4], const uint32_t a[4],
                                         uint32_t b0, uint32_t b1) {
    asm volatile(
        "mma.sync.aligned.m16n8k16.row.col.f32.bf16.bf16.f32 "
        "{%0,%1,%2,%3}, {%4,%5,%6,%7}, {%8,%9}, {%0,%1,%2,%3};\n"
        : "+f"(c[0]), "+f"(c[1]), "+f"(c[2]), "+f"(c[3])
        : "r"(a[0]), "r"(a[1]), "r"(a[2]), "r"(a[3]), "r"(b0), "r"(b1));
}

// cp.async loader: 128x256 bf16 tile (64KB), XOR-swizzled 16B chunks, 256 threads
__device__ __forceinline__ void load_tile(uint32_t sdst_base,
                                          const __nv_bfloat16* gsrc, int tid) {
    int c = tid & 31, r8 = tid >> 5;
    #pragma unroll
    for (int p = 0; p < 16; p++) {
        int row = p * 8 + r8;
        uint32_t sdst = sdst_base + row * 512 + (((uint32_t)(c ^ (row & 7))) << 4);
        cp_async16(sdst, gsrc + (size_t)row * D + c * 8);
    }
}

// ---------------- kernel 1: norms + exact diagonal + g_part zeroing --------
__global__ void norm_kernel(const float4* __restrict__ a4, const float4* __restrict__ b4) {
    // zero the partial-sum slots (rewritten each run only where covered)
    int gt = blockIdx.x * 256 + threadIdx.x;
    if (gt < MAXN * SLOTS) g_part[gt] = 0.f;

    int w = threadIdx.x >> 5, lane = threadIdx.x & 31;
    int row = blockIdx.x * 8 + w;
    const float4* ar = a4 + (size_t)row * (D / 4);
    const float4* br = b4 + (size_t)row * (D / 4);
    float4 a0 = ar[lane * 2], a1 = ar[lane * 2 + 1];
    float4 b0 = br[lane * 2], b1 = br[lane * 2 + 1];

    float sa = a0.x*a0.x + a0.y*a0.y + a0.z*a0.z + a0.w*a0.w
             + a1.x*a1.x + a1.y*a1.y + a1.z*a1.z + a1.w*a1.w;
    float sb = b0.x*b0.x + b0.y*b0.y + b0.z*b0.z + b0.w*b0.w
             + b1.x*b1.x + b1.y*b1.y + b1.z*b1.z + b1.w*b1.w;
    float sd = a0.x*b0.x + a0.y*b0.y + a0.z*b0.z + a0.w*b0.w
             + a1.x*b1.x + a1.y*b1.y + a1.z*b1.z + a1.w*b1.w;
    #pragma unroll
    for (int o = 16; o; o >>= 1) {
        sa += __shfl_xor_sync(0xffffffffu, sa, o);
        sb += __shfl_xor_sync(0xffffffffu, sb, o);
        sd += __shfl_xor_sync(0xffffffffu, sd, o);
    }
    float ia = rsqrtf(fmaxf(sa, 1e-16f));
    float ib = rsqrtf(fmaxf(sb, 1e-16f));
    if (lane == 0) g_diag[row] = sd * ia * ib * INV_T;

    float fa = ia * LOG2E_OVER_T;
    __nv_bfloat162 p0 = __floats2bfloat162_rn(a0.x*fa, a0.y*fa);
    __nv_bfloat162 p1 = __floats2bfloat162_rn(a0.z*fa, a0.w*fa);
    __nv_bfloat162 p2 = __floats2bfloat162_rn(a1.x*fa, a1.y*fa);
    __nv_bfloat162 p3 = __floats2bfloat162_rn(a1.z*fa, a1.w*fa);
    uint4 ua = { *(uint32_t*)&p0, *(uint32_t*)&p1, *(uint32_t*)&p2, *(uint32_t*)&p3 };
    *(uint4*)(g_a + (size_t)row * D + lane * 8) = ua;

    __nv_bfloat162 q0 = __floats2bfloat162_rn(b0.x*ib, b0.y*ib);
    __nv_bfloat162 q1 = __floats2bfloat162_rn(b0.z*ib, b0.w*ib);
    __nv_bfloat162 q2 = __floats2bfloat162_rn(b1.x*ib, b1.y*ib);
    __nv_bfloat162 q3 = __floats2bfloat162_rn(b1.z*ib, b1.w*ib);
    uint4 ub = { *(uint32_t*)&q0, *(uint32_t*)&q1, *(uint32_t*)&q2, *(uint32_t*)&q3 };
    *(uint4*)(g_b + (size_t)row * D + lane * 8) = ub;
}

// ---------------- kernel 2: balanced-partition HMMA GEMM + ex2 -------------
// 148 CTAs; CTA i owns tiles [i*4096/148, (i+1)*4096/148) (27-28 tiles),
// crossing at most one row-block boundary (A reload). 8 warps, 32x64 warp tile.
__global__ __launch_bounds__(256, 1) void sim_lse_kernel() {
    extern __shared__ char sm[];
    uint32_t sbase = smem_u32(sm);
    int tid = threadIdx.x, w = tid >> 5, lane = tid & 31;
    int cta = blockIdx.x;
    int gStart = (cta * NTOT) / GRIDZ;
    int gEnd   = ((cta + 1) * NTOT) / GRIDZ;

    int wr = (w & 3) * 32;        // warp row offset
    int wc = (w >> 2) * 64;       // warp col offset
    int g2 = lane >> 3, l3 = lane & 7;
    uint32_t rk = (uint32_t)(l3 >> 1);

    uint32_t abase[2], boff[4];
    {
        uint32_t c0a = (uint32_t)(((g2 >> 1) ^ (l3 & 1)) << 4);
        uint32_t c0b = (uint32_t)(((g2 & 1) ^ (l3 & 1)) << 4);
        #pragma unroll
        for (int mt = 0; mt < 2; mt++) {
            int row = wr + mt * 16 + (g2 & 1) * 8 + l3;
            abase[mt] = sbase + SM_A + row * 512 + c0a;
        }
        #pragma unroll
        for (int nt = 0; nt < 4; nt++) {
            int n = wc + nt * 16 + (g2 >> 1) * 8 + l3;
            boff[nt] = (uint32_t)(n * 512) + c0b;
        }
    }

    int rb = gStart >> 6;          // current row-block
    // prologue: A(rb) + B(gStart) in one group
    load_tile(sbase + SM_A, g_a + (size_t)rb * BM * D, tid);
    load_tile(sbase + SM_B0 + (gStart & 1) * 65536,
              g_b + (size_t)(gStart & (CTPB - 1)) * BN * D, tid);
    CP_COMMIT();

    float acc[2][8][4];
    #pragma unroll
    for (int mt = 0; mt < 2; mt++)
        #pragma unroll
        for (int j = 0; j < 8; j++)
            acc[mt][j][0] = acc[mt][j][1] = acc[mt][j][2] = acc[mt][j][3] = 0.f;
    float rs0[2] = {0, 0}, rs1[2] = {0, 0};
    float* partial = (float*)(sm + SM_PART);

    for (int g = gStart; g < gEnd; g++) {
        __syncthreads();           // prior reads of buffer (g+1)&1 done
        if (g + 1 < gEnd)
            load_tile(sbase + SM_B0 + ((g + 1) & 1) * 65536,
                      g_b + (size_t)((g + 1) & (CTPB - 1)) * BN * D, tid);
        CP_COMMIT();               // empty group keeps wait_group 1 valid
        CP_WAIT1();                // all but last group retired -> tile g (and A) ready
        __syncthreads();

        uint32_t bbuf = sbase + SM_B0 + (g & 1) * 65536;

        #pragma unroll
        for (int kk = 0; kk < 16; kk++) {
            uint32_t koff = ((uint32_t)(kk ^ rk)) << 5;
            uint32_t af[2][4], bf[4][4];
            #pragma unroll
            for (int mt = 0; mt < 2; mt++) ldsm_x4(af[mt], abase[mt] + koff);
            #pragma unroll
            for (int nt = 0; nt < 4; nt++) ldsm_x4(bf[nt], bbuf + boff[nt] + koff);
            #pragma unroll
            for (int mt = 0; mt < 2; mt++) {
                #pragma unroll
                for (int nt = 0; nt < 4; nt++) {
                    mma_bf16(acc[mt][nt * 2],     af[mt], bf[nt][0], bf[nt][1]);
                    mma_bf16(acc[mt][nt * 2 + 1], af[mt], bf[nt][2], bf[nt][3]);
                }
            }
        }
        // epilogue: logits in log2 units, |x| <= 29 -> plain sum of 2^x
        #pragma unroll
        for (int mt = 0; mt < 2; mt++)
            #pragma unroll
            for (int j = 0; j < 8; j++) {
                rs0[mt] += ex2f(acc[mt][j][0]) + ex2f(acc[mt][j][1]);
                rs1[mt] += ex2f(acc[mt][j][2]) + ex2f(acc[mt][j][3]);
                acc[mt][j][0] = acc[mt][j][1] = acc[mt][j][2] = acc[mt][j][3] = 0.f;
            }

        // row-block boundary (or range end): flush row partials
        if ((((g + 1) & (CTPB - 1)) == 0) || (g + 1 == gEnd)) {
            #pragma unroll
            for (int mt = 0; mt < 2; mt++) {
                rs0[mt] += __shfl_xor_sync(0xffffffffu, rs0[mt], 1);
                rs0[mt] += __shfl_xor_sync(0xffffffffu, rs0[mt], 2);
                rs1[mt] += __shfl_xor_sync(0xffffffffu, rs1[mt], 1);
                rs1[mt] += __shfl_xor_sync(0xffffffffu, rs1[mt], 2);
            }
            if ((lane & 3) == 0) {
                int half = (w >> 2) * 128;
                #pragma unroll
                for (int mt = 0; mt < 2; mt++) {
                    partial[half + wr + mt * 16 + (lane >> 2)]     = rs0[mt];
                    partial[half + wr + mt * 16 + 8 + (lane >> 2)] = rs1[mt];
                }
            }
            __syncthreads();       // also guarantees all warps left the k-loop
            // slot = rank of this CTA among CTAs covering rb
            int ft = rb << 6;
            int i0 = (ft * GRIDZ) / NTOT;
            while (((i0 + 1) * NTOT) / GRIDZ <= ft) i0++;
            int slot = cta - i0;   // 0..SLOTS-1
            if (tid < 128)
                g_part[(size_t)(rb * BM + tid) * SLOTS + slot] =
                    partial[tid] + partial[128 + tid];
            rs0[0] = rs0[1] = rs1[0] = rs1[1] = 0.f;
            if (g + 1 < gEnd && (((g + 1) & (CTPB - 1)) == 0)) {
                rb = (g + 1) >> 6;                 // reload A for next row-block
                load_tile(sbase + SM_A, g_a + (size_t)rb * BM * D, tid);
                CP_COMMIT();       // ordered before next B commit; WAIT1 covers it
            }
        }
    }
}

// ---------------- kernel 3: final loss ------------------------------------
__global__ void reduce_kernel(float* __restrict__ out, int N) {
    __shared__ float s[1024];
    int t = threadIdx.x;
    float acc = 0.f;
    for (int i = t; i < N; i += 1024) {
        const float* p = g_part + (size_t)i * SLOTS;
        float sum2 = (p[0] + p[1]) + (p[2] + p[3]);
        acc += __logf(sum2) - g_diag[i];       // log(sum 2^l2) = LSE (natural)
    }
    s[t] = acc;
    __syncthreads();
    for (int o = 512; o; o >>= 1) {
        if (t < o) s[t] += s[t + o];
        __syncthreads();
    }
    if (t == 0) out[0] = s[0] / (float)N;
}

// ---------------- launch ---------------------------------------------------
extern "C" void kernel_launch(void* const* d_in, const int* in_sizes, int n_in,
                              void* d_out, int out_size) {
    const float* a = (const float*)d_in[0];
    const float* b = (const float*)d_in[1];
    int N = in_sizes[0] / D;   // 8192

    cudaFuncSetAttribute(sim_lse_kernel,
                         cudaFuncAttributeMaxDynamicSharedMemorySize, SM_TOTAL);

    norm_kernel<<<N / 8, 256>>>((const float4*)a, (const float4*)b);
    sim_lse_kernel<<<GRIDZ, 256, SM_TOTAL>>>();
    reduce_kernel<<<1, 1024>>>((float*)d_out, N);
}